// round 1
// baseline (speedup 1.0000x reference)
#include <cuda_runtime.h>
#include <math.h>

#define B 8
#define D 256
#define NN 1024   // h*w (query positions)
#define MM 1024   // key positions
#define H 8
#define KD 64
#define VD 64
#define QR 512    // KD*H rows of packed WqT
#define KVR 128   // 64 K rows + 64 V rows

// ---------------- scratch (device globals; no allocation) ----------------
__device__ float g_WqT[QR * D];         // [rk=k*8+h][d]
__device__ float g_WkvT[KVR * D];       // [r][d]  r<64: Wk^T, r>=64: Wv^T
__device__ float g_Q[B * KD * NN * H];  // [b][k][n*8+h]
__device__ float g_KV[B * KVR * MM];    // [b][r][m]

// ---------------- kernel 0: pack weights ----------------
__global__ void pack_weights(const float* __restrict__ Wq,
                             const float* __restrict__ Wk,
                             const float* __restrict__ Wv) {
    int i = blockIdx.x * blockDim.x + threadIdx.x;
    if (i < QR * D) {
        int rk = i / D, d = i % D;
        int k = rk >> 3, h = rk & 7;
        g_WqT[i] = Wq[h * (D * KD) + d * KD + k];
    }
    if (i < KVR * D) {
        int r = i / D, d = i % D;
        g_WkvT[i] = (r < 64) ? Wk[d * KD + r] : Wv[d * VD + (r - 64)];
    }
}

// ---------------- kernel 1: projection GEMM ----------------
// C[r, n] = sum_d A[r, d] * X[b, d, n].  Tile 128x128, 256 threads, 8x8/thread.
// MODE 0: A = g_WqT (512 rows), write g_Q[b][k][n*8+h]
// MODE 1: A = g_WkvT (128 rows), write g_KV[b][r][m]
template <int MODE>
__global__ void __launch_bounds__(256) proj_gemm(const float* __restrict__ X) {
    const int b = blockIdx.z, rt = blockIdx.y, nt = blockIdx.x;
    const int r0 = rt * 128, n0 = nt * 128;
    const float* A = (MODE == 0) ? g_WqT : g_WkvT;
    const float* Xb = X + b * (D * NN);

    __shared__ float As[128 * 17];   // [rr][c], padded
    __shared__ float Xs[16 * 128];   // [c][nn]

    float acc[8][8] = {};
    const int tr = threadIdx.x >> 4;   // 0..15
    const int tn = threadIdx.x & 15;   // 0..15

    for (int dc = 0; dc < D; dc += 16) {
#pragma unroll
        for (int i = 0; i < 8; i++) {
            int idx = threadIdx.x + i * 256;
            int rr = idx >> 4, c = idx & 15;
            As[rr * 17 + c] = A[(r0 + rr) * D + dc + c];
        }
#pragma unroll
        for (int i = 0; i < 8; i++) {
            int idx = threadIdx.x + i * 256;
            int c = idx >> 7, nn = idx & 127;
            Xs[c * 128 + nn] = Xb[(dc + c) * NN + n0 + nn];
        }
        __syncthreads();
#pragma unroll
        for (int c = 0; c < 16; c++) {
            float ra[8], rx[8];
#pragma unroll
            for (int i = 0; i < 8; i++) ra[i] = As[(tr + 16 * i) * 17 + c];
#pragma unroll
            for (int j = 0; j < 8; j++) rx[j] = Xs[c * 128 + tn + 16 * j];
#pragma unroll
            for (int i = 0; i < 8; i++)
#pragma unroll
                for (int j = 0; j < 8; j++) acc[i][j] += ra[i] * rx[j];
        }
        __syncthreads();
    }

#pragma unroll
    for (int i = 0; i < 8; i++) {
        int r = r0 + tr + 16 * i;
#pragma unroll
        for (int j = 0; j < 8; j++) {
            int n = n0 + tn + 16 * j;
            if (MODE == 0) {
                int k = r >> 3, h = r & 7;
                g_Q[b * (KD * NN * H) + k * (NN * H) + n * 8 + h] = acc[i][j];
            } else {
                g_KV[b * (KVR * MM) + r * MM + n] = acc[i][j];
            }
        }
    }
}

// ---------------- kernel 2: fused main ----------------
// Per block: batch b, 32 query positions (256 nh columns, nh = n*8+h).
//  loop m in chunks of 32:
//    logits[32m][256nh] = K_chunk^T-dot-Q      (GEMM1)
//    softmax over h (8 contiguous values per (m,n))
//    O[64v][256nh] += V_chunk @ attn            (GEMM2, register accum)
//  epilogue: res[256d][32n] = Wo[256,512] @ O-as-[512vh][32n]
// smem regions (floats):
//   [0, 16896)        Qs [64][256]   / later Os [512][33]
//   [16896, 20992)    KVs [128][32]
//   [20992, 29216)    Ats [32][256]  / later Wo_s [32][257]
#define SMEM_FLOATS 29216
#define SMEM_BYTES (SMEM_FLOATS * 4)

__global__ void __launch_bounds__(256, 1) mqa_main(const float* __restrict__ Wo,
                                                   float* __restrict__ out) {
    extern __shared__ float sm[];
    float* Qs = sm;              // [64][256]
    float* KVs = sm + 16896;     // [128][32]
    float* Ats = sm + 20992;     // [32][256]

    const int b = blockIdx.y;
    const int n0 = blockIdx.x * 32;
    const int tid = threadIdx.x;
    const int lane = tid & 31;
    const int wgrp = tid >> 5;   // 0..7

    // load Q tile: rows k=0..63, 256 contiguous nh columns
    const float* Qg = g_Q + b * (KD * NN * H) + n0 * 8;
#pragma unroll
    for (int i = 0; i < 64; i++) {
        int idx = tid + i * 256;
        int k = idx >> 8, col = idx & 255;
        Qs[k * 256 + col] = Qg[k * (NN * H) + col];
    }

    float Oacc[8][8] = {};
    const float* KVb = g_KV + b * (KVR * MM);

    for (int m0 = 0; m0 < MM; m0 += 32) {
        __syncthreads();   // prev phase3 done with KVs/Ats (and first-iter Qs ready)
#pragma unroll
        for (int i = 0; i < 16; i++) {
            int idx = tid + i * 256;
            int r = idx >> 5, mc = idx & 31;
            KVs[r * 32 + mc] = KVb[r * MM + m0 + mc];
        }
        __syncthreads();

        // ---- phase 1: logits [32][256] ----
        {
            float acc[4][8] = {};
            const int ml = wgrp * 4;
#pragma unroll
            for (int k = 0; k < 64; k++) {
                float rk_[4], rq[8];
#pragma unroll
                for (int i = 0; i < 4; i++) rk_[i] = KVs[k * 32 + ml + i];  // broadcast
#pragma unroll
                for (int j = 0; j < 8; j++) rq[j] = Qs[k * 256 + lane + 32 * j];
#pragma unroll
                for (int i = 0; i < 4; i++)
#pragma unroll
                    for (int j = 0; j < 8; j++) acc[i][j] += rk_[i] * rq[j];
            }
#pragma unroll
            for (int i = 0; i < 4; i++)
#pragma unroll
                for (int j = 0; j < 8; j++)
                    Ats[(ml + i) * 256 + lane + 32 * j] = acc[i][j];
        }
        __syncthreads();

        // ---- phase 2: softmax over h (8 contiguous) ----
#pragma unroll
        for (int p4 = 0; p4 < 4; p4++) {
            int p = tid + p4 * 256;      // (m,n) pair
            float* row = Ats + (p >> 5) * 256 + (p & 31) * 8;
            float mx = row[0];
#pragma unroll
            for (int j = 1; j < 8; j++) mx = fmaxf(mx, row[j]);
            float e[8], s = 0.f;
#pragma unroll
            for (int j = 0; j < 8; j++) { e[j] = __expf((row[j] - mx) * 0.125f); s += e[j]; }
            float inv = 1.f / s;
#pragma unroll
            for (int j = 0; j < 8; j++) row[j] = e[j] * inv;
        }
        __syncthreads();

        // ---- phase 3: O += V_chunk @ attn ----
        {
            const int v0 = wgrp * 8;
#pragma unroll
            for (int mc = 0; mc < 32; mc++) {
                float rv[8], ra[8];
#pragma unroll
                for (int i = 0; i < 8; i++) rv[i] = KVs[(64 + v0 + i) * 32 + mc]; // broadcast
#pragma unroll
                for (int j = 0; j < 8; j++) ra[j] = Ats[mc * 256 + lane + 32 * j];
#pragma unroll
                for (int i = 0; i < 8; i++)
#pragma unroll
                    for (int j = 0; j < 8; j++) Oacc[i][j] += rv[i] * ra[j];
            }
        }
    }
    __syncthreads();

    // ---- epilogue: stage O as [vh=v*8+h][n], padded stride 33 ----
    float* Os = sm;          // reuse Qs region: 512*33 = 16896
    {
        const int v0 = wgrp * 8;
#pragma unroll
        for (int i = 0; i < 8; i++)
#pragma unroll
            for (int j = 0; j < 8; j++) {
                int nh = lane + 32 * j;
                Os[((v0 + i) * 8 + (nh & 7)) * 33 + (nh >> 3)] = Oacc[i][j];
            }
    }

    // res[256d][32n] = Wo[256][512] @ Os[512][32]
    float* Wo_s = sm + 20992;   // [32][257]
    float racc[8][4] = {};
    const int dg = tid >> 3;    // 0..31
    const int ng = tid & 7;     // 0..7
    for (int vh0 = 0; vh0 < 512; vh0 += 32) {
        __syncthreads();
#pragma unroll
        for (int i = 0; i < 32; i++) {
            int idx = tid + i * 256;
            int d = idx >> 5, c = idx & 31;
            Wo_s[c * 257 + d] = Wo[d * 512 + vh0 + c];
        }
        __syncthreads();
#pragma unroll
        for (int c = 0; c < 32; c++) {
            float rw[8], ro[4];
#pragma unroll
            for (int i = 0; i < 8; i++) rw[i] = Wo_s[c * 257 + dg + 32 * i];
#pragma unroll
            for (int jj = 0; jj < 4; jj++) ro[jj] = Os[(vh0 + c) * 33 + ng + 8 * jj];
#pragma unroll
            for (int i = 0; i < 8; i++)
#pragma unroll
                for (int jj = 0; jj < 4; jj++) racc[i][jj] += rw[i] * ro[jj];
        }
    }

    float* ob = out + b * (D * NN);
#pragma unroll
    for (int i = 0; i < 8; i++)
#pragma unroll
        for (int jj = 0; jj < 4; jj++)
            ob[(dg + 32 * i) * NN + n0 + ng + 8 * jj] = racc[i][jj];
}

// ---------------- launcher ----------------
extern "C" void kernel_launch(void* const* d_in, const int* in_sizes, int n_in,
                              void* d_out, int out_size) {
    const float* x     = (const float*)d_in[0];
    const float* value = (const float*)d_in[1];
    const float* Wq    = (const float*)d_in[2];
    const float* Wk    = (const float*)d_in[3];
    const float* Wv    = (const float*)d_in[4];
    const float* Wo    = (const float*)d_in[5];
    float* out = (float*)d_out;

    pack_weights<<<(QR * D + 255) / 256, 256>>>(Wq, Wk, Wv);
    proj_gemm<0><<<dim3(NN / 128, QR / 128, B), 256>>>(x);
    proj_gemm<1><<<dim3(MM / 128, KVR / 128, B), 256>>>(value);

    cudaFuncSetAttribute(mqa_main, cudaFuncAttributeMaxDynamicSharedMemorySize, SMEM_BYTES);
    mqa_main<<<dim3(NN / 32, B), 256, SMEM_BYTES>>>(Wo, out);
}

// round 2
// speedup vs baseline: 1.0812x; 1.0812x over previous
#include <cuda_runtime.h>
#include <math.h>

#define B 8
#define D 256
#define NN 1024   // query positions
#define MM 1024   // key positions
#define H 8
#define KD 64
#define VD 64
#define QR 512    // KD*H rows of packed WqT
#define KVR 128   // 64 K rows + 64 V rows

// ---------------- scratch ----------------
__device__ float g_WqT[QR * D];          // [rk=k*8+h][d]
__device__ float g_WkvT[KVR * D];        // [r][d]
__device__ float g_Q[B * KD * NN * H];   // [b][k][n*8+h]
__device__ float g_K[B * KD * MM];       // [b][k][m]
__device__ float g_VT[B * MM * VD];      // [b][m][v]   (transposed!)

// ---------------- kernel 0: pack weights ----------------
__global__ void pack_weights(const float* __restrict__ Wq,
                             const float* __restrict__ Wk,
                             const float* __restrict__ Wv) {
    int i = blockIdx.x * blockDim.x + threadIdx.x;
    if (i < QR * D) {
        int rk = i / D, d = i % D;
        int k = rk >> 3, h = rk & 7;
        g_WqT[i] = Wq[h * (D * KD) + d * KD + k];
    }
    if (i < KVR * D) {
        int r = i / D, d = i % D;
        g_WkvT[i] = (r < 64) ? Wk[d * KD + r] : Wv[d * VD + (r - 64)];
    }
}

// ---------------- kernel 1: projection GEMM (vectorized) ----------------
// C[r, n] = sum_d A[r, d] * X[b, d, n].  128x128 tile, 256 thr, 8x8/thread.
template <int MODE>
__global__ void __launch_bounds__(256) proj_gemm(const float* __restrict__ X) {
    const int b = blockIdx.z, r0 = blockIdx.y * 128, n0 = blockIdx.x * 128;
    const float* A = (MODE == 0) ? g_WqT : g_WkvT;
    const float* Xb = X + b * (D * NN);

    __shared__ float As[16 * 136];   // [c][rr], stride 136 (16B-aligned rows)
    __shared__ float Xs[16 * 128];   // [c][nn]

    float acc[8][8] = {};
    const int tid = threadIdx.x;
    const int tr = tid >> 4;    // 0..15
    const int tn = tid & 15;    // 0..15

    for (int dc = 0; dc < D; dc += 16) {
#pragma unroll
        for (int i = 0; i < 8; i++) {
            int idx = tid + i * 256;
            int rr = idx >> 4, c = idx & 15;
            As[c * 136 + rr] = A[(r0 + rr) * D + dc + c];
        }
#pragma unroll
        for (int i = 0; i < 8; i++) {
            int idx = tid + i * 256;
            int c = idx >> 7, nn = idx & 127;
            Xs[c * 128 + nn] = Xb[(dc + c) * NN + n0 + nn];
        }
        __syncthreads();
#pragma unroll
        for (int c = 0; c < 16; c++) {
            float4 a0 = *(const float4*)&As[c * 136 + tr * 4];
            float4 a1 = *(const float4*)&As[c * 136 + 64 + tr * 4];
            float4 x0 = *(const float4*)&Xs[c * 128 + tn * 4];
            float4 x1 = *(const float4*)&Xs[c * 128 + 64 + tn * 4];
            float ra[8] = {a0.x, a0.y, a0.z, a0.w, a1.x, a1.y, a1.z, a1.w};
            float rx[8] = {x0.x, x0.y, x0.z, x0.w, x1.x, x1.y, x1.z, x1.w};
#pragma unroll
            for (int i = 0; i < 8; i++)
#pragma unroll
                for (int j = 0; j < 8; j++) acc[i][j] += ra[i] * rx[j];
        }
        __syncthreads();
    }

#pragma unroll
    for (int i = 0; i < 8; i++) {
        int r = r0 + tr * 4 + (i & 3) + (i >> 2) * 64;
#pragma unroll
        for (int j = 0; j < 8; j++) {
            int n = n0 + tn * 4 + (j & 3) + (j >> 2) * 64;
            if (MODE == 0) {
                int k = r >> 3, h = r & 7;
                g_Q[b * (KD * NN * H) + k * (NN * H) + n * 8 + h] = acc[i][j];
            } else {
                if (r < 64) g_K[b * (KD * MM) + r * MM + n] = acc[i][j];
                else        g_VT[b * (MM * VD) + n * VD + (r - 64)] = acc[i][j];
            }
        }
    }
}

// ---------------- kernel 2: fused main ----------------
// smem (floats):
//   Qs  [64][256]  @ 0       (16384)
//   KVs [64][32]   @ 16384   (2048)   K chunk
//   VTs [32][68]   @ 18432   (2176)   V chunk transposed, pad 68
//   Ats [32][256]  @ 20608   (8192)
// epilogue overlay:
//   Os  [512][36]  @ 0       (18432)
//   WoS [32][260]  @ 18432   (8320)
#define SMEM_FLOATS 28800
#define SMEM_BYTES (SMEM_FLOATS * 4)

__global__ void __launch_bounds__(256, 1) mqa_main(const float* __restrict__ Wo,
                                                   float* __restrict__ out) {
    extern __shared__ float sm[];
    float* Qs  = sm;
    float* KVs = sm + 16384;
    float* VTs = sm + 18432;
    float* Ats = sm + 20608;

    const int b = blockIdx.y;
    const int n0 = blockIdx.x * 32;
    const int tid = threadIdx.x;
    const int lane = tid & 31;
    const int wgrp = tid >> 5;
    const int c0 = lane * 4;

    // load Q tile as float4 copies
    {
        const float* Qg = g_Q + b * (KD * NN * H) + n0 * 8;
#pragma unroll
        for (int i = 0; i < 16; i++) {
            int idx = tid + i * 256;          // 4096 float4s
            int k = idx >> 6, c4 = idx & 63;
            ((float4*)Qs)[k * 64 + c4] =
                *(const float4*)&Qg[k * (NN * H) + c4 * 4];
        }
    }

    float Oacc[8][8] = {};
    const float* Kb = g_K + b * (KD * MM);
    const float* VTb = g_VT + b * (MM * VD);

    for (int m0 = 0; m0 < MM; m0 += 32) {
        __syncthreads();   // prev phase3 done with KVs/VTs/Ats (iter0: Q store done)
#pragma unroll
        for (int i = 0; i < 8; i++) {         // K chunk [64][32]
            int idx = tid + i * 256;
            int r = idx >> 5, mc = idx & 31;
            KVs[r * 32 + mc] = Kb[r * MM + m0 + mc];
        }
#pragma unroll
        for (int i = 0; i < 8; i++) {         // V chunk transposed [32][68pad]
            int idx = tid + i * 256;
            int v = idx & 63, mc = idx >> 6;
            VTs[mc * 68 + v] = VTb[(m0 + mc) * VD + v];
        }
        __syncthreads();

        // ---- phase 1: logits + softmax (regs) + store attn ----
        {
            float acc[4][8] = {};
            const int ml = wgrp * 4;
#pragma unroll 8
            for (int k = 0; k < 64; k++) {
                float4 kk = *(const float4*)&KVs[k * 32 + ml];
                float4 q0 = *(const float4*)&Qs[k * 256 + c0];
                float4 q1 = *(const float4*)&Qs[k * 256 + 128 + c0];
                float kr[4] = {kk.x, kk.y, kk.z, kk.w};
                float qr[8] = {q0.x, q0.y, q0.z, q0.w, q1.x, q1.y, q1.z, q1.w};
#pragma unroll
                for (int i = 0; i < 4; i++)
#pragma unroll
                    for (int j = 0; j < 8; j++) acc[i][j] += kr[i] * qr[j];
            }
            // softmax over heads: lane pair (l, l^1) holds the 8 h's of one (m,n)
#pragma unroll
            for (int i = 0; i < 4; i++) {
#pragma unroll
                for (int half = 0; half < 2; half++) {
                    float* a = &acc[i][half * 4];
                    float mx = fmaxf(fmaxf(a[0], a[1]), fmaxf(a[2], a[3]));
                    mx = fmaxf(mx, __shfl_xor_sync(0xffffffffu, mx, 1));
                    float s = 0.f;
#pragma unroll
                    for (int j = 0; j < 4; j++) {
                        a[j] = __expf((a[j] - mx) * 0.125f);
                        s += a[j];
                    }
                    s += __shfl_xor_sync(0xffffffffu, s, 1);
                    float inv = __fdividef(1.f, s);
#pragma unroll
                    for (int j = 0; j < 4; j++) a[j] *= inv;
                }
                *(float4*)&Ats[(ml + i) * 256 + c0] =
                    make_float4(acc[i][0], acc[i][1], acc[i][2], acc[i][3]);
                *(float4*)&Ats[(ml + i) * 256 + 128 + c0] =
                    make_float4(acc[i][4], acc[i][5], acc[i][6], acc[i][7]);
            }
        }
        __syncthreads();

        // ---- phase 3: O += V^T-chunk outer attn ----
        {
            const int v0 = wgrp * 8;
#pragma unroll 8
            for (int mc = 0; mc < 32; mc++) {
                float4 va = *(const float4*)&VTs[mc * 68 + v0];
                float4 vb = *(const float4*)&VTs[mc * 68 + v0 + 4];
                float4 a0 = *(const float4*)&Ats[mc * 256 + c0];
                float4 a1 = *(const float4*)&Ats[mc * 256 + 128 + c0];
                float rv[8] = {va.x, va.y, va.z, va.w, vb.x, vb.y, vb.z, vb.w};
                float ra[8] = {a0.x, a0.y, a0.z, a0.w, a1.x, a1.y, a1.z, a1.w};
#pragma unroll
                for (int i = 0; i < 8; i++)
#pragma unroll
                    for (int j = 0; j < 8; j++) Oacc[i][j] += rv[i] * ra[j];
            }
        }
    }
    __syncthreads();

    // ---- epilogue: stage O as [vh][n] (pad 36) ----
    float* Os = sm;            // 512*36 = 18432 floats (over Qs+KVs)
    float* WoS = sm + 18432;   // [32][260]
    {
        const int v0 = wgrp * 8;
#pragma unroll
        for (int i = 0; i < 8; i++)
#pragma unroll
            for (int j = 0; j < 8; j++) {
                int h = 4 * (lane & 1) + (j & 3);
                int n = (j >> 2) * 16 + (lane >> 1);
                Os[((v0 + i) * 8 + h) * 36 + n] = Oacc[i][j];
            }
    }

    // res[256d][32n] = Wo[256][512] @ Os[512][32]
    float racc[8][4] = {};
    const int d0 = (tid >> 3) * 8;   // 8 consecutive d
    const int ng = (tid & 7) * 4;    // 4 consecutive n
    for (int vh0 = 0; vh0 < 512; vh0 += 32) {
        __syncthreads();
#pragma unroll
        for (int i = 0; i < 32; i++) {
            int idx = tid + i * 256;
            int c = idx & 31, d = idx >> 5;
            WoS[c * 260 + d] = Wo[d * 512 + vh0 + c];
        }
        __syncthreads();
#pragma unroll 8
        for (int c = 0; c < 32; c++) {
            float4 w0 = *(const float4*)&WoS[c * 260 + d0];
            float4 w1 = *(const float4*)&WoS[c * 260 + d0 + 4];
            float4 o4 = *(const float4*)&Os[(vh0 + c) * 36 + ng];
            float rw[8] = {w0.x, w0.y, w0.z, w0.w, w1.x, w1.y, w1.z, w1.w};
            float ro[4] = {o4.x, o4.y, o4.z, o4.w};
#pragma unroll
            for (int i = 0; i < 8; i++)
#pragma unroll
                for (int jj = 0; jj < 4; jj++) racc[i][jj] += rw[i] * ro[jj];
        }
    }

    float* ob = out + b * (D * NN);
#pragma unroll
    for (int i = 0; i < 8; i++) {
        *(float4*)&ob[(d0 + i) * NN + n0 + ng] =
            make_float4(racc[i][0], racc[i][1], racc[i][2], racc[i][3]);
    }
}

// ---------------- launcher ----------------
extern "C" void kernel_launch(void* const* d_in, const int* in_sizes, int n_in,
                              void* d_out, int out_size) {
    const float* x     = (const float*)d_in[0];
    const float* value = (const float*)d_in[1];
    const float* Wq    = (const float*)d_in[2];
    const float* Wk    = (const float*)d_in[3];
    const float* Wv    = (const float*)d_in[4];
    const float* Wo    = (const float*)d_in[5];
    float* out = (float*)d_out;

    pack_weights<<<(QR * D + 255) / 256, 256>>>(Wq, Wk, Wv);
    proj_gemm<0><<<dim3(NN / 128, QR / 128, B), 256>>>(x);
    proj_gemm<1><<<dim3(MM / 128, KVR / 128, B), 256>>>(value);

    cudaFuncSetAttribute(mqa_main, cudaFuncAttributeMaxDynamicSharedMemorySize, SMEM_BYTES);
    mqa_main<<<dim3(NN / 32, B), 256, SMEM_BYTES>>>(Wo, out);
}

// round 3
// speedup vs baseline: 2.1088x; 1.9505x over previous
#include <cuda_runtime.h>
#include <math.h>
#include <stdint.h>

#define B 8
#define D 256
#define NN 1024
#define MM 1024
#define H 8
#define KD 64
#define VD 64
#define QR 512
#define KVR 128

// strides (floats)
#define QS 264   // Qs [64][QS]
#define KS 40    // KVs [64][KS]
#define VS 72    // VTs [32][VS]
#define AS 264   // Ats [32][AS]
#define OSS 524  // Os  [32][OSS]  (epilogue, [n][vh])
#define WS 36    // WoS [256][WS]

#define Q_OFF   0
#define KV_OFF  16896            // 64*264
#define VT_OFF  (KV_OFF + 64*KS) // 19456
#define AT_OFF  (VT_OFF + 32*VS) // 21760
#define SMEM_FLOATS (AT_OFF + 32*AS)   // 30208
#define SMEM_BYTES (SMEM_FLOATS * 4)
#define WOS_OFF 16768            // after Os (32*524)

__device__ float g_WqT[QR * D];
__device__ float g_WkvT[KVR * D];
__device__ float g_Q[B * KD * NN * H];   // [b][k][n*8+h], tf32-rounded
__device__ float g_K[B * KD * MM];       // [b][k][m], tf32-rounded
__device__ float g_VT[B * MM * VD];      // [b][m][v], tf32-rounded

__device__ __forceinline__ float to_tf32(float x) {
    uint32_t u;
    asm("cvt.rna.tf32.f32 %0, %1;" : "=r"(u) : "f"(x));
    return __uint_as_float(u);
}

__device__ __forceinline__ void mma8(float* c, const float* a, const float* b) {
    asm volatile(
        "mma.sync.aligned.m16n8k8.row.col.f32.tf32.tf32.f32 "
        "{%0,%1,%2,%3}, {%4,%5,%6,%7}, {%8,%9}, {%0,%1,%2,%3};\n"
        : "+f"(c[0]), "+f"(c[1]), "+f"(c[2]), "+f"(c[3])
        : "r"(__float_as_uint(a[0])), "r"(__float_as_uint(a[1])),
          "r"(__float_as_uint(a[2])), "r"(__float_as_uint(a[3])),
          "r"(__float_as_uint(b[0])), "r"(__float_as_uint(b[1])));
}

// ---------------- kernel 0: pack weights ----------------
__global__ void pack_weights(const float* __restrict__ Wq,
                             const float* __restrict__ Wk,
                             const float* __restrict__ Wv) {
    int i = blockIdx.x * blockDim.x + threadIdx.x;
    if (i < QR * D) {
        int rk = i / D, d = i % D;
        int k = rk >> 3, h = rk & 7;
        g_WqT[i] = Wq[h * (D * KD) + d * KD + k];
    }
    if (i < KVR * D) {
        int r = i / D, d = i % D;
        g_WkvT[i] = (r < 64) ? Wk[d * KD + r] : Wv[d * VD + (r - 64)];
    }
}

// ---------------- kernel 1: projection GEMM (fp32, tf32-rounded output) ----------------
template <int MODE>
__global__ void __launch_bounds__(256) proj_gemm(const float* __restrict__ X) {
    const int b = blockIdx.z, r0 = blockIdx.y * 128, n0 = blockIdx.x * 128;
    const float* A = (MODE == 0) ? g_WqT : g_WkvT;
    const float* Xb = X + b * (D * NN);

    __shared__ float As[16 * 136];
    __shared__ float Xs[16 * 128];

    float acc[8][8] = {};
    const int tid = threadIdx.x;
    const int tr = tid >> 4, tn = tid & 15;

    for (int dc = 0; dc < D; dc += 16) {
#pragma unroll
        for (int i = 0; i < 8; i++) {
            int idx = tid + i * 256;
            int rr = idx >> 4, c = idx & 15;
            As[c * 136 + rr] = A[(r0 + rr) * D + dc + c];
        }
#pragma unroll
        for (int i = 0; i < 8; i++) {
            int idx = tid + i * 256;
            int c = idx >> 7, nn = idx & 127;
            Xs[c * 128 + nn] = Xb[(dc + c) * NN + n0 + nn];
        }
        __syncthreads();
#pragma unroll
        for (int c = 0; c < 16; c++) {
            float4 a0 = *(const float4*)&As[c * 136 + tr * 4];
            float4 a1 = *(const float4*)&As[c * 136 + 64 + tr * 4];
            float4 x0 = *(const float4*)&Xs[c * 128 + tn * 4];
            float4 x1 = *(const float4*)&Xs[c * 128 + 64 + tn * 4];
            float ra[8] = {a0.x, a0.y, a0.z, a0.w, a1.x, a1.y, a1.z, a1.w};
            float rx[8] = {x0.x, x0.y, x0.z, x0.w, x1.x, x1.y, x1.z, x1.w};
#pragma unroll
            for (int i = 0; i < 8; i++)
#pragma unroll
                for (int j = 0; j < 8; j++) acc[i][j] += ra[i] * rx[j];
        }
        __syncthreads();
    }

#pragma unroll
    for (int i = 0; i < 8; i++) {
        int r = r0 + tr * 4 + (i & 3) + (i >> 2) * 64;
#pragma unroll
        for (int j = 0; j < 8; j++) {
            int n = n0 + tn * 4 + (j & 3) + (j >> 2) * 64;
            float v = to_tf32(acc[i][j]);
            if (MODE == 0) {
                int k = r >> 3, h = r & 7;
                g_Q[b * (KD * NN * H) + k * (NN * H) + n * 8 + h] = v;
            } else {
                if (r < 64) g_K[b * (KD * MM) + r * MM + n] = v;
                else        g_VT[b * (MM * VD) + n * VD + (r - 64)] = v;
            }
        }
    }
}

// ---------------- kernel 2: fused main (tf32 tensor cores) ----------------
__global__ void __launch_bounds__(256, 1) mqa_main(const float* __restrict__ Wo,
                                                   float* __restrict__ out) {
    extern __shared__ float sm[];
    float* Qs  = sm + Q_OFF;
    float* KVs = sm + KV_OFF;
    float* VTs = sm + VT_OFF;
    float* Ats = sm + AT_OFF;

    const int b = blockIdx.y;
    const int n0 = blockIdx.x * 32;
    const int tid = threadIdx.x;
    const int lane = tid & 31;
    const int wgrp = tid >> 5;
    const int gid = lane >> 2;   // 0..7
    const int tig = lane & 3;    // 0..3
    const int wn0 = wgrp * 32;   // warp nh slice

    // load Q tile [64][256] (already tf32-rounded)
    {
        const float* Qg = g_Q + b * (KD * NN * H) + n0 * 8;
#pragma unroll
        for (int i = 0; i < 16; i++) {
            int idx = tid + i * 256;
            int k = idx >> 6, c4 = idx & 63;
            *(float4*)&Qs[k * QS + c4 * 4] = *(const float4*)&Qg[k * (NN * H) + c4 * 4];
        }
    }

    float Oacc[4][4][4] = {};   // [vi][ni][reg]
    const float* Kb  = g_K  + b * (KD * MM);
    const float* VTb = g_VT + b * (MM * VD);

    for (int m0 = 0; m0 < MM; m0 += 32) {
        __syncthreads();
#pragma unroll
        for (int i = 0; i < 8; i++) {       // K chunk [64][32] -> KVs
            int idx = tid + i * 256;
            int r = idx >> 5, mc = idx & 31;
            KVs[r * KS + mc] = Kb[r * MM + m0 + mc];
        }
#pragma unroll
        for (int i = 0; i < 8; i++) {       // V chunk [32][64] -> VTs
            int idx = tid + i * 256;
            int mc = idx >> 6, v = idx & 63;
            VTs[mc * VS + v] = VTb[(m0 + mc) * VD + v];
        }
        __syncthreads();

        // ---- phase 1: logits via mma, softmax on fragments ----
        {
            float c1[2][4][4] = {};
#pragma unroll
            for (int kc = 0; kc < 8; kc++) {
                const int k0 = kc * 8;
                float a[2][4], bf[4][2];
#pragma unroll
                for (int mi = 0; mi < 2; mi++) {
                    a[mi][0] = KVs[(k0 + tig) * KS + mi * 16 + gid];
                    a[mi][1] = KVs[(k0 + tig) * KS + mi * 16 + gid + 8];
                    a[mi][2] = KVs[(k0 + tig + 4) * KS + mi * 16 + gid];
                    a[mi][3] = KVs[(k0 + tig + 4) * KS + mi * 16 + gid + 8];
                }
#pragma unroll
                for (int ni = 0; ni < 4; ni++) {
                    bf[ni][0] = Qs[(k0 + tig) * QS + wn0 + ni * 8 + gid];
                    bf[ni][1] = Qs[(k0 + tig + 4) * QS + wn0 + ni * 8 + gid];
                }
#pragma unroll
                for (int mi = 0; mi < 2; mi++)
#pragma unroll
                    for (int ni = 0; ni < 4; ni++) mma8(c1[mi][ni], a[mi], bf[ni]);
            }
            // softmax over heads (8 cols of each n8 tile) + store attn (tf32)
#pragma unroll
            for (int mi = 0; mi < 2; mi++)
#pragma unroll
                for (int ni = 0; ni < 4; ni++) {
                    float* cc = c1[mi][ni];
#pragma unroll
                    for (int rr = 0; rr < 2; rr++) {
                        float& x0 = cc[rr * 2];
                        float& x1 = cc[rr * 2 + 1];
                        float mx = fmaxf(x0, x1);
                        mx = fmaxf(mx, __shfl_xor_sync(0xffffffffu, mx, 1));
                        mx = fmaxf(mx, __shfl_xor_sync(0xffffffffu, mx, 2));
                        float e0 = __expf((x0 - mx) * 0.125f);
                        float e1 = __expf((x1 - mx) * 0.125f);
                        float s = e0 + e1;
                        s += __shfl_xor_sync(0xffffffffu, s, 1);
                        s += __shfl_xor_sync(0xffffffffu, s, 2);
                        float inv = __fdividef(1.f, s);
                        x0 = to_tf32(e0 * inv);
                        x1 = to_tf32(e1 * inv);
                    }
                    *(float2*)&Ats[(mi * 16 + gid) * AS + wn0 + ni * 8 + tig * 2] =
                        make_float2(cc[0], cc[1]);
                    *(float2*)&Ats[(mi * 16 + gid + 8) * AS + wn0 + ni * 8 + tig * 2] =
                        make_float2(cc[2], cc[3]);
                }
        }
        __syncthreads();

        // ---- phase 3: O += V @ attn via mma ----
#pragma unroll
        for (int kc = 0; kc < 4; kc++) {
            const int k0 = kc * 8;
            float a[4][4], bf[4][2];
#pragma unroll
            for (int vi = 0; vi < 4; vi++) {
                a[vi][0] = VTs[(k0 + tig) * VS + vi * 16 + gid];
                a[vi][1] = VTs[(k0 + tig) * VS + vi * 16 + gid + 8];
                a[vi][2] = VTs[(k0 + tig + 4) * VS + vi * 16 + gid];
                a[vi][3] = VTs[(k0 + tig + 4) * VS + vi * 16 + gid + 8];
            }
#pragma unroll
            for (int ni = 0; ni < 4; ni++) {
                bf[ni][0] = Ats[(k0 + tig) * AS + wn0 + ni * 8 + gid];
                bf[ni][1] = Ats[(k0 + tig + 4) * AS + wn0 + ni * 8 + gid];
            }
#pragma unroll
            for (int vi = 0; vi < 4; vi++)
#pragma unroll
                for (int ni = 0; ni < 4; ni++) mma8(Oacc[vi][ni], a[vi], bf[ni]);
        }
    }
    __syncthreads();

    // ---- epilogue: stage O as [n][vh] (tf32), then res = Wo @ O ----
    float* Os = sm;             // [32][OSS]
    float* WoS = sm + WOS_OFF;  // [256][WS]
    {
#pragma unroll
        for (int vi = 0; vi < 4; vi++)
#pragma unroll
            for (int ni = 0; ni < 4; ni++) {
                int nl = wgrp * 4 + ni;
                int v = vi * 16 + gid;
                *(float2*)&Os[nl * OSS + v * 8 + tig * 2] =
                    make_float2(to_tf32(Oacc[vi][ni][0]), to_tf32(Oacc[vi][ni][1]));
                *(float2*)&Os[nl * OSS + (v + 8) * 8 + tig * 2] =
                    make_float2(to_tf32(Oacc[vi][ni][2]), to_tf32(Oacc[vi][ni][3]));
            }
    }

    float racc[2][4][4] = {};   // [mi(d)][ni][reg]
    const int wd0 = wgrp * 32;
    for (int vh0 = 0; vh0 < 512; vh0 += 32) {
        __syncthreads();
#pragma unroll
        for (int i = 0; i < 32; i++) {
            int idx = tid + i * 256;
            int c = idx & 31, d = idx >> 5;
            WoS[d * WS + c] = to_tf32(Wo[d * 512 + vh0 + c]);
        }
        __syncthreads();
#pragma unroll
        for (int kc = 0; kc < 4; kc++) {
            const int k0 = kc * 8;
            float a[2][4], bf[4][2];
#pragma unroll
            for (int mi = 0; mi < 2; mi++) {
                a[mi][0] = WoS[(wd0 + mi * 16 + gid) * WS + k0 + tig];
                a[mi][1] = WoS[(wd0 + mi * 16 + gid + 8) * WS + k0 + tig];
                a[mi][2] = WoS[(wd0 + mi * 16 + gid) * WS + k0 + tig + 4];
                a[mi][3] = WoS[(wd0 + mi * 16 + gid + 8) * WS + k0 + tig + 4];
            }
#pragma unroll
            for (int ni = 0; ni < 4; ni++) {
                bf[ni][0] = Os[(ni * 8 + gid) * OSS + vh0 + k0 + tig];
                bf[ni][1] = Os[(ni * 8 + gid) * OSS + vh0 + k0 + tig + 4];
            }
#pragma unroll
            for (int mi = 0; mi < 2; mi++)
#pragma unroll
                for (int ni = 0; ni < 4; ni++) mma8(racc[mi][ni], a[mi], bf[ni]);
        }
    }

    float* ob = out + b * (D * NN);
#pragma unroll
    for (int mi = 0; mi < 2; mi++)
#pragma unroll
        for (int ni = 0; ni < 4; ni++) {
            int d = wd0 + mi * 16 + gid;
            *(float2*)&ob[d * NN + n0 + ni * 8 + tig * 2] =
                make_float2(racc[mi][ni][0], racc[mi][ni][1]);
            *(float2*)&ob[(d + 8) * NN + n0 + ni * 8 + tig * 2] =
                make_float2(racc[mi][ni][2], racc[mi][ni][3]);
        }
}

// ---------------- launcher ----------------
extern "C" void kernel_launch(void* const* d_in, const int* in_sizes, int n_in,
                              void* d_out, int out_size) {
    const float* x     = (const float*)d_in[0];
    const float* value = (const float*)d_in[1];
    const float* Wq    = (const float*)d_in[2];
    const float* Wk    = (const float*)d_in[3];
    const float* Wv    = (const float*)d_in[4];
    const float* Wo    = (const float*)d_in[5];
    float* out = (float*)d_out;

    pack_weights<<<(QR * D + 255) / 256, 256>>>(Wq, Wk, Wv);
    proj_gemm<0><<<dim3(NN / 128, QR / 128, B), 256>>>(x);
    proj_gemm<1><<<dim3(MM / 128, KVR / 128, B), 256>>>(value);

    cudaFuncSetAttribute(mqa_main, cudaFuncAttributeMaxDynamicSharedMemorySize, SMEM_BYTES);
    mqa_main<<<dim3(NN / 32, B), 256, SMEM_BYTES>>>(Wo, out);
}

// round 4
// speedup vs baseline: 2.3891x; 1.1329x over previous
#include <cuda_runtime.h>
#include <math.h>
#include <stdint.h>

#define B 8
#define D 256
#define NN 1024
#define MM 1024
#define H 8
#define KD 64
#define VD 64
#define QR 512
#define KVR 128

// main-kernel smem layout (floats)
#define QFRAG_OFF 0        // 16384 (8 wgrp * 8 kc * 256)
#define KST_OFF   16384    // 2 stages * 2048
#define VST_OFF   20480    // 2 stages * 2048
// epilogue overlay: Os[32][524] @0 (16768), WoS[256][36] @16768 (9216)
#define OSS 524
#define WS  36
#define WOS_OFF 16768
#define SMEM_FLOATS 25984
#define SMEM_BYTES (SMEM_FLOATS * 4)

#define QSCALE 0.1803368801f   // 0.125 * log2(e)

__device__ float g_WqT[QR * D];
__device__ float g_WkvT[KVR * D];
__device__ float g_Q[B * KD * NN * H];   // [b][k][n*8+h], tf32, pre-scaled
__device__ float g_K[B * 32 * 8 * 256];  // fragment-packed per 32-m chunk
__device__ float g_V[B * 32 * 4 * 512];  // fragment-packed per 32-m chunk

__device__ __forceinline__ float to_tf32(float x) {
    uint32_t u;
    asm("cvt.rna.tf32.f32 %0, %1;" : "=r"(u) : "f"(x));
    return __uint_as_float(u);
}
__device__ __forceinline__ float ex2(float x) {
    float r;
    asm("ex2.approx.f32 %0, %1;" : "=f"(r) : "f"(x));
    return r;
}
__device__ __forceinline__ float rcp(float x) {
    float r;
    asm("rcp.approx.f32 %0, %1;" : "=f"(r) : "f"(x));
    return r;
}
__device__ __forceinline__ void mma8(float* c, const float* a, const float* b) {
    asm volatile(
        "mma.sync.aligned.m16n8k8.row.col.f32.tf32.tf32.f32 "
        "{%0,%1,%2,%3}, {%4,%5,%6,%7}, {%8,%9}, {%0,%1,%2,%3};\n"
        : "+f"(c[0]), "+f"(c[1]), "+f"(c[2]), "+f"(c[3])
        : "r"(__float_as_uint(a[0])), "r"(__float_as_uint(a[1])),
          "r"(__float_as_uint(a[2])), "r"(__float_as_uint(a[3])),
          "r"(__float_as_uint(b[0])), "r"(__float_as_uint(b[1])));
}

// ---------------- kernel 0: pack weights ----------------
__global__ void pack_weights(const float* __restrict__ Wq,
                             const float* __restrict__ Wk,
                             const float* __restrict__ Wv) {
    int i = blockIdx.x * blockDim.x + threadIdx.x;
    if (i < QR * D) {
        int rk = i / D, d = i % D;
        int k = rk >> 3, h = rk & 7;
        g_WqT[i] = Wq[h * (D * KD) + d * KD + k];
    }
    if (i < KVR * D) {
        int r = i / D, d = i % D;
        g_WkvT[i] = (r < 64) ? Wk[d * KD + r] : Wv[d * VD + (r - 64)];
    }
}

// ---------------- kernel 1: projection GEMM ----------------
template <int MODE>
__global__ void __launch_bounds__(256) proj_gemm(const float* __restrict__ X) {
    const int b = blockIdx.z, r0 = blockIdx.y * 128, n0 = blockIdx.x * 128;
    const float* A = (MODE == 0) ? g_WqT : g_WkvT;
    const float* Xb = X + b * (D * NN);

    __shared__ float As[16 * 136];
    __shared__ float Xs[16 * 128];

    float acc[8][8] = {};
    const int tid = threadIdx.x;
    const int tr = tid >> 4, tn = tid & 15;

    for (int dc = 0; dc < D; dc += 16) {
#pragma unroll
        for (int i = 0; i < 8; i++) {
            int idx = tid + i * 256;
            int rr = idx >> 4, c = idx & 15;
            As[c * 136 + rr] = A[(r0 + rr) * D + dc + c];
        }
#pragma unroll
        for (int i = 0; i < 8; i++) {
            int idx = tid + i * 256;
            int c = idx >> 7, nn = idx & 127;
            Xs[c * 128 + nn] = Xb[(dc + c) * NN + n0 + nn];
        }
        __syncthreads();
#pragma unroll
        for (int c = 0; c < 16; c++) {
            float4 a0 = *(const float4*)&As[c * 136 + tr * 4];
            float4 a1 = *(const float4*)&As[c * 136 + 64 + tr * 4];
            float4 x0 = *(const float4*)&Xs[c * 128 + tn * 4];
            float4 x1 = *(const float4*)&Xs[c * 128 + 64 + tn * 4];
            float ra[8] = {a0.x, a0.y, a0.z, a0.w, a1.x, a1.y, a1.z, a1.w};
            float rx[8] = {x0.x, x0.y, x0.z, x0.w, x1.x, x1.y, x1.z, x1.w};
#pragma unroll
            for (int i = 0; i < 8; i++)
#pragma unroll
                for (int j = 0; j < 8; j++) acc[i][j] += ra[i] * rx[j];
        }
        __syncthreads();
    }

#pragma unroll
    for (int i = 0; i < 8; i++) {
        int r = r0 + tr * 4 + (i & 3) + (i >> 2) * 64;
#pragma unroll
        for (int j = 0; j < 8; j++) {
            int n = n0 + tn * 4 + (j & 3) + (j >> 2) * 64;
            if (MODE == 0) {
                int k = r >> 3, h = r & 7;
                g_Q[b * (KD * NN * H) + k * (NN * H) + n * 8 + h] =
                    to_tf32(acc[i][j] * QSCALE);
            } else {
                float v = to_tf32(acc[i][j]);
                if (r < 64) {
                    int k = r, m = n;
                    int addr = (((b * 32 + (m >> 5)) * 8 + (k >> 3)) << 8)
                             + (((m >> 4) & 1) << 7)
                             + (((m & 7) * 4 + (k & 3)) << 2)
                             + (((k >> 2) & 1) << 1) + ((m >> 3) & 1);
                    g_K[addr] = v;
                } else {
                    int vv = r - 64, m = n, mc = m & 31;
                    int addr = (((b * 32 + (m >> 5)) * 4 + (mc >> 3)) << 9)
                             + ((vv >> 4) << 7)
                             + (((vv & 7) * 4 + (mc & 3)) << 2)
                             + (((mc >> 2) & 1) << 1) + ((vv >> 3) & 1);
                    g_V[addr] = v;
                }
            }
        }
    }
}

// ---------------- kernel 2: fused main ----------------
__global__ void __launch_bounds__(256, 1) mqa_main(const float* __restrict__ Wo,
                                                   float* __restrict__ out) {
    extern __shared__ float sm[];
    float* Qs = sm + QFRAG_OFF;

    const int b = blockIdx.y;
    const int n0 = blockIdx.x * 32;
    const int tid = threadIdx.x;
    const int lane = tid & 31;
    const int wgrp = tid >> 5;
    const int gid = lane >> 2;
    const int tig = lane & 3;

    // stage Q into fragment-packed smem (once)
    {
        const float* Qg = g_Q + b * (KD * NN * H) + n0 * 8;
#pragma unroll
        for (int i = 0; i < 16; i++) {
            int idx = tid + i * 256;
            int k = idx >> 6;
            int c4 = (idx & 63) * 4;
            float4 qv = *(const float4*)&Qg[k * (NN * H) + c4];
            int kc = k >> 3, ktig = k & 3, e = (k >> 2) & 1;
#pragma unroll
            for (int t = 0; t < 4; t++) {
                int col = c4 + t;
                int wg = col >> 5, ni = (col >> 3) & 3, gi = col & 7;
                int f = ni * 2 + e;
                Qs[wg * 2048 + kc * 256 + (f >> 2) * 128 + (gi * 4 + ktig) * 4 + (f & 3)] =
                    ((const float*)&qv)[t];
            }
        }
    }

    float Oacc[4][4][4] = {};
    const float* Kg = g_K + b * 65536;
    const float* Vg = g_V + b * 65536;
    const float* Qw = Qs + wgrp * 2048;

    float4 kr0 = *(const float4*)&Kg[tid * 4];
    float4 kr1 = *(const float4*)&Kg[1024 + tid * 4];
    float4 vr0 = *(const float4*)&Vg[tid * 4];
    float4 vr1 = *(const float4*)&Vg[1024 + tid * 4];

    int s = 0;
    for (int mch = 0; mch < 32; mch++) {
        float* Ks = sm + KST_OFF + s * 2048;
        float* Vs = sm + VST_OFF + s * 2048;
        *(float4*)&Ks[tid * 4] = kr0;
        *(float4*)&Ks[1024 + tid * 4] = kr1;
        *(float4*)&Vs[tid * 4] = vr0;
        *(float4*)&Vs[1024 + tid * 4] = vr1;
        __syncthreads();
        if (mch < 31) {
            int nb = (mch + 1) * 2048;
            kr0 = *(const float4*)&Kg[nb + tid * 4];
            kr1 = *(const float4*)&Kg[nb + 1024 + tid * 4];
            vr0 = *(const float4*)&Vg[nb + tid * 4];
            vr1 = *(const float4*)&Vg[nb + 1024 + tid * 4];
        }

        // ---- phase 1: logits ----
        float c1[2][4][4] = {};
#pragma unroll
        for (int kc = 0; kc < 8; kc++) {
            float4 a0 = *(const float4*)&Ks[kc * 256 + lane * 4];
            float4 a1 = *(const float4*)&Ks[kc * 256 + 128 + lane * 4];
            float4 q0 = *(const float4*)&Qw[kc * 256 + lane * 4];
            float4 q1 = *(const float4*)&Qw[kc * 256 + 128 + lane * 4];
            float b0[2] = {q0.x, q0.y}, b1[2] = {q0.z, q0.w};
            float b2[2] = {q1.x, q1.y}, b3[2] = {q1.z, q1.w};
            mma8(c1[0][0], &a0.x, b0); mma8(c1[0][1], &a0.x, b1);
            mma8(c1[0][2], &a0.x, b2); mma8(c1[0][3], &a0.x, b3);
            mma8(c1[1][0], &a1.x, b0); mma8(c1[1][1], &a1.x, b1);
            mma8(c1[1][2], &a1.x, b2); mma8(c1[1][3], &a1.x, b3);
        }

        // ---- softmax over heads (quad shuffles; logits pre-scaled to exp2 domain) ----
#pragma unroll
        for (int mi = 0; mi < 2; mi++)
#pragma unroll
            for (int ni = 0; ni < 4; ni++) {
                float* cc = c1[mi][ni];
                float e0 = ex2(cc[0]), e1 = ex2(cc[1]);
                float sa = e0 + e1;
                sa += __shfl_xor_sync(0xffffffffu, sa, 1);
                sa += __shfl_xor_sync(0xffffffffu, sa, 2);
                float ra = rcp(sa);
                cc[0] = to_tf32(e0 * ra); cc[1] = to_tf32(e1 * ra);
                float e2 = ex2(cc[2]), e3 = ex2(cc[3]);
                float sb = e2 + e3;
                sb += __shfl_xor_sync(0xffffffffu, sb, 1);
                sb += __shfl_xor_sync(0xffffffffu, sb, 2);
                float rb = rcp(sb);
                cc[2] = to_tf32(e2 * rb); cc[3] = to_tf32(e3 * rb);
            }

        // ---- transpose attn C-frags -> B-frags via shuffles ----
        float bt[4][4][2];
        const int src = tig * 4 + (gid >> 1);
        const bool og = gid & 1;
#pragma unroll
        for (int mi = 0; mi < 2; mi++)
#pragma unroll
            for (int ni = 0; ni < 4; ni++) {
                float* cc = c1[mi][ni];
                float t0 = __shfl_sync(0xffffffffu, cc[0], src);
                float t1 = __shfl_sync(0xffffffffu, cc[1], src);
                float t2 = __shfl_sync(0xffffffffu, cc[2], src);
                float t3 = __shfl_sync(0xffffffffu, cc[3], src);
                float u0 = __shfl_sync(0xffffffffu, cc[0], src + 16);
                float u1 = __shfl_sync(0xffffffffu, cc[1], src + 16);
                float u2 = __shfl_sync(0xffffffffu, cc[2], src + 16);
                float u3 = __shfl_sync(0xffffffffu, cc[3], src + 16);
                bt[2 * mi][ni][0] = og ? t1 : t0;
                bt[2 * mi][ni][1] = og ? u1 : u0;
                bt[2 * mi + 1][ni][0] = og ? t3 : t2;
                bt[2 * mi + 1][ni][1] = og ? u3 : u2;
            }

        // ---- phase 3: O += V @ attn ----
#pragma unroll
        for (int kc3 = 0; kc3 < 4; kc3++) {
            float4 v0 = *(const float4*)&Vs[kc3 * 512 + lane * 4];
            float4 v1 = *(const float4*)&Vs[kc3 * 512 + 128 + lane * 4];
            float4 v2 = *(const float4*)&Vs[kc3 * 512 + 256 + lane * 4];
            float4 v3 = *(const float4*)&Vs[kc3 * 512 + 384 + lane * 4];
#pragma unroll
            for (int ni = 0; ni < 4; ni++) {
                mma8(Oacc[0][ni], &v0.x, bt[kc3][ni]);
                mma8(Oacc[1][ni], &v1.x, bt[kc3][ni]);
                mma8(Oacc[2][ni], &v2.x, bt[kc3][ni]);
                mma8(Oacc[3][ni], &v3.x, bt[kc3][ni]);
            }
        }
        s ^= 1;
    }
    __syncthreads();

    // ---- epilogue: stage O as [n][vh] (tf32), then res = Wo @ O ----
    float* Os = sm;
    float* WoS = sm + WOS_OFF;
    {
#pragma unroll
        for (int vi = 0; vi < 4; vi++)
#pragma unroll
            for (int ni = 0; ni < 4; ni++) {
                int nl = wgrp * 4 + ni;
                int v = vi * 16 + gid;
                *(float2*)&Os[nl * OSS + v * 8 + tig * 2] =
                    make_float2(to_tf32(Oacc[vi][ni][0]), to_tf32(Oacc[vi][ni][1]));
                *(float2*)&Os[nl * OSS + (v + 8) * 8 + tig * 2] =
                    make_float2(to_tf32(Oacc[vi][ni][2]), to_tf32(Oacc[vi][ni][3]));
            }
    }

    float racc[2][4][4] = {};
    const int wd0 = wgrp * 32;
    for (int vh0 = 0; vh0 < 512; vh0 += 32) {
        __syncthreads();
#pragma unroll
        for (int i = 0; i < 32; i++) {
            int idx = tid + i * 256;
            int c = idx & 31, d = idx >> 5;
            WoS[d * WS + c] = to_tf32(Wo[d * 512 + vh0 + c]);
        }
        __syncthreads();
#pragma unroll
        for (int kc = 0; kc < 4; kc++) {
            const int k0 = kc * 8;
            float a[2][4], bf[4][2];
#pragma unroll
            for (int mi = 0; mi < 2; mi++) {
                a[mi][0] = WoS[(wd0 + mi * 16 + gid) * WS + k0 + tig];
                a[mi][1] = WoS[(wd0 + mi * 16 + gid + 8) * WS + k0 + tig];
                a[mi][2] = WoS[(wd0 + mi * 16 + gid) * WS + k0 + tig + 4];
                a[mi][3] = WoS[(wd0 + mi * 16 + gid + 8) * WS + k0 + tig + 4];
            }
#pragma unroll
            for (int ni = 0; ni < 4; ni++) {
                bf[ni][0] = Os[(ni * 8 + gid) * OSS + vh0 + k0 + tig];
                bf[ni][1] = Os[(ni * 8 + gid) * OSS + vh0 + k0 + tig + 4];
            }
#pragma unroll
            for (int mi = 0; mi < 2; mi++)
#pragma unroll
                for (int ni = 0; ni < 4; ni++) mma8(racc[mi][ni], a[mi], bf[ni]);
        }
    }

    float* ob = out + b * (D * NN);
#pragma unroll
    for (int mi = 0; mi < 2; mi++)
#pragma unroll
        for (int ni = 0; ni < 4; ni++) {
            int d = wd0 + mi * 16 + gid;
            *(float2*)&ob[d * NN + n0 + ni * 8 + tig * 2] =
                make_float2(racc[mi][ni][0], racc[mi][ni][1]);
            *(float2*)&ob[(d + 8) * NN + n0 + ni * 8 + tig * 2] =
                make_float2(racc[mi][ni][2], racc[mi][ni][3]);
        }
}

// ---------------- launcher ----------------
extern "C" void kernel_launch(void* const* d_in, const int* in_sizes, int n_in,
                              void* d_out, int out_size) {
    const float* x     = (const float*)d_in[0];
    const float* value = (const float*)d_in[1];
    const float* Wq    = (const float*)d_in[2];
    const float* Wk    = (const float*)d_in[3];
    const float* Wv    = (const float*)d_in[4];
    const float* Wo    = (const float*)d_in[5];
    float* out = (float*)d_out;

    pack_weights<<<(QR * D + 255) / 256, 256>>>(Wq, Wk, Wv);
    proj_gemm<0><<<dim3(NN / 128, QR / 128, B), 256>>>(x);
    proj_gemm<1><<<dim3(MM / 128, KVR / 128, B), 256>>>(value);

    cudaFuncSetAttribute(mqa_main, cudaFuncAttributeMaxDynamicSharedMemorySize, SMEM_BYTES);
    mqa_main<<<dim3(NN / 32, B), 256, SMEM_BYTES>>>(Wo, out);
}